// round 2
// baseline (speedup 1.0000x reference)
#include <cuda_runtime.h>

#define NB 256
#define NT 96
#define ND 32
#define NH 128
#define NOUT 32
#define NF 24
#define BC 64
#define NCTA 128

#define F_OFS 0
#define F_CNT (NB*NF*NOUT)
#define A_OFS F_CNT
#define A_CNT (NB*NT*ND)
#define B_OFS (A_OFS + A_CNT)
#define B_CNT (NB*NF*ND)
#define O_OFS (B_OFS + B_CNT)

typedef unsigned long long ull;

// ------------- scratch (no allocs allowed) -------------
__device__ float g_h[ND*NB*NH];
__device__ float g_c[ND*NB*NH];
__device__ float g_gn[ND*NB*NH];
__device__ float g_den[NB*ND];
__device__ float g_mu[NB*ND*NOUT];
__device__ float g_bt[NB*ND];
__device__ float g_prev[ND*NB];

struct EncSmem {
    ull   hdup[BC][NH];   // h duplicated into both f32x2 lanes
    float gs[BC][NH];     // g_n staging
    float Fa_s[NH];
    float xs[BC];
    float es[BC];
    float den_s[BC];
};

// ------------- packed f32x2 helpers -------------
__device__ __forceinline__ ull pack2(float lo, float hi) {
    ull r;
    asm("mov.b64 %0, {%1, %2};" : "=l"(r)
        : "r"(__float_as_uint(lo)), "r"(__float_as_uint(hi)));
    return r;
}
__device__ __forceinline__ ull dup2(float v) {
    ull r; unsigned u = __float_as_uint(v);
    asm("mov.b64 %0, {%1, %1};" : "=l"(r) : "r"(u));
    return r;
}
__device__ __forceinline__ void unpack2(ull p, float &lo, float &hi) {
    unsigned a, b;
    asm("mov.b64 {%0, %1}, %2;" : "=r"(a), "=r"(b) : "l"(p));
    lo = __uint_as_float(a); hi = __uint_as_float(b);
}
__device__ __forceinline__ void fma2(ull &acc, ull a, ull b) {
    asm("fma.rn.f32x2 %0, %1, %2, %0;" : "+l"(acc) : "l"(a), "l"(b));
}

__device__ __forceinline__ float sigf(float x) {
    return __fdividef(1.f, 1.f + __expf(-x));
}
__device__ __forceinline__ float tanhfast(float x) {
    float e = __expf(-2.f * x);
    return __fdividef(1.f - e, 1.f + e);
}

// ------------- one gate GEMM -------------
// thread: rows b0t..b0t+3, cols hk0..hk0+7. acc[bi*4+p] = cols (hk0+2p, hk0+2p+1).
__device__ __forceinline__ void gate_gemm(
    const float* __restrict__ Wd, const float* __restrict__ Ud,
    const float* __restrict__ bd, const ull (*hd)[NH],
    const float* __restrict__ xs, int hk0, int b0t, ull acc[16])
{
    float4 u0 = *(const float4*)(Ud + hk0);
    float4 u1 = *(const float4*)(Ud + hk0 + 4);
    float4 v0 = *(const float4*)(bd + hk0);
    float4 v1 = *(const float4*)(bd + hk0 + 4);
#pragma unroll
    for (int bi = 0; bi < 4; ++bi) {
        float xv = xs[b0t + bi];
        acc[bi*4+0] = pack2(fmaf(xv,u0.x,v0.x), fmaf(xv,u0.y,v0.y));
        acc[bi*4+1] = pack2(fmaf(xv,u0.z,v0.z), fmaf(xv,u0.w,v0.w));
        acc[bi*4+2] = pack2(fmaf(xv,u1.x,v1.x), fmaf(xv,u1.y,v1.y));
        acc[bi*4+3] = pack2(fmaf(xv,u1.z,v1.z), fmaf(xv,u1.w,v1.w));
    }
    const float* wp = Wd + hk0;
#pragma unroll 4
    for (int k = 0; k < NH; ++k) {
        ulonglong2 w01 = *(const ulonglong2*)(wp);
        ulonglong2 w23 = *(const ulonglong2*)(wp + 4);
        wp += NH;
#pragma unroll
        for (int bi = 0; bi < 4; ++bi) {
            ull hh = hd[b0t + bi][k];
            fma2(acc[bi*4+0], hh, w01.x);
            fma2(acc[bi*4+1], hh, w01.y);
            fma2(acc[bi*4+2], hh, w23.x);
            fma2(acc[bi*4+3], hh, w23.y);
        }
    }
}

// ------------- full LSTM cell for this thread's 32 elements -------------
__device__ __forceinline__ void cell_step(
    const float* __restrict__ Wjd, const float* __restrict__ Wid,
    const float* __restrict__ Wfd, const float* __restrict__ Wod,
    const float* __restrict__ Ujd, const float* __restrict__ Uid,
    const float* __restrict__ Ufd, const float* __restrict__ Uod,
    const float* __restrict__ bjd, const float* __restrict__ bid,
    const float* __restrict__ bfd, const float* __restrict__ bod,
    const ull (*hd)[NH], const float* __restrict__ xs,
    int hk0, int b0t, float* c, float* h2)
{
    ull acc[16];
    gate_gemm(Wjd, Ujd, bjd, hd, xs, hk0, b0t, acc);     // j
#pragma unroll
    for (int e = 0; e < 16; ++e) {
        float lo, hi; unpack2(acc[e], lo, hi);
        int ii = (e >> 2) * 8 + (e & 3) * 2;
        h2[ii] = tanhfast(lo); h2[ii+1] = tanhfast(hi);
    }
    gate_gemm(Wid, Uid, bid, hd, xs, hk0, b0t, acc);     // i  (h2 <- i*j)
#pragma unroll
    for (int e = 0; e < 16; ++e) {
        float lo, hi; unpack2(acc[e], lo, hi);
        int ii = (e >> 2) * 8 + (e & 3) * 2;
        h2[ii] *= sigf(lo); h2[ii+1] *= sigf(hi);
    }
    gate_gemm(Wfd, Ufd, bfd, hd, xs, hk0, b0t, acc);     // f  (c <- c*f + i*j)
#pragma unroll
    for (int e = 0; e < 16; ++e) {
        float lo, hi; unpack2(acc[e], lo, hi);
        int ii = (e >> 2) * 8 + (e & 3) * 2;
        c[ii]   = fmaf(c[ii],   sigf(lo), h2[ii]);
        c[ii+1] = fmaf(c[ii+1], sigf(hi), h2[ii+1]);
    }
    gate_gemm(Wod, Uod, bod, hd, xs, hk0, b0t, acc);     // o  (h2 <- o*tanh(c))
#pragma unroll
    for (int e = 0; e < 16; ++e) {
        float lo, hi; unpack2(acc[e], lo, hi);
        int ii = (e >> 2) * 8 + (e & 3) * 2;
        h2[ii]   = sigf(lo) * tanhfast(c[ii]);
        h2[ii+1] = sigf(hi) * tanhfast(c[ii+1]);
    }
}

// ------------- mu / bt for the next fc step (uses hdup = h, gs = g_n) -------------
__device__ __forceinline__ void compute_mu_bt(
    EncSmem* s, int d, int b0, int tid,
    const float* __restrict__ Phi_w, const float* __restrict__ Phi_b,
    const float* __restrict__ Fbw, const float* __restrict__ Fbb)
{
    int outc = tid & 31;
    int bg = tid >> 5;                      // 8 groups x 8 batch rows
    float acc[8];
    float pb = Phi_b[outc];
#pragma unroll
    for (int r = 0; r < 8; ++r) acc[r] = pb;
#pragma unroll 2
    for (int k = 0; k < NH; ++k) {
        float pg = Phi_w[k*NOUT + outc];
        float ph = Phi_w[(NH + k)*NOUT + outc];
#pragma unroll
        for (int r = 0; r < 8; ++r) {
            int b = bg*8 + r;
            float hv = *(const float*)&s->hdup[b][k];   // low lane = h
            acc[r] = fmaf(s->gs[b][k], pg, acc[r]);
            acc[r] = fmaf(hv, ph, acc[r]);
        }
    }
#pragma unroll
    for (int r = 0; r < 8; ++r)
        g_mu[(((size_t)(b0 + bg*8 + r))*ND + d)*NOUT + outc] = acc[r];

    if (tid < BC) {
        int b = tid;
        float a = Fbb[0];
        for (int k = 0; k < NH; ++k) {
            float hv = *(const float*)&s->hdup[b][k];
            a = fmaf(s->gs[b][k], Fbw[k], a);
            a = fmaf(hv, Fbw[NH + k], a);
        }
        g_bt[(size_t)(b0 + b)*ND + d] = __expf(tanhfast(a));
    }
}

// ================= encoder: 96 steps persistent =================
__global__ void __launch_bounds__(256, 1) enc_kernel(
    const float* __restrict__ x,
    const float* __restrict__ Uj, const float* __restrict__ Ui,
    const float* __restrict__ Uf, const float* __restrict__ Uo,
    const float* __restrict__ Wj, const float* __restrict__ Wi,
    const float* __restrict__ Wf, const float* __restrict__ Wo,
    const float* __restrict__ bj, const float* __restrict__ bi_,
    const float* __restrict__ bf, const float* __restrict__ bo,
    const float* __restrict__ Fa, const float* __restrict__ Fab,
    const float* __restrict__ Phi_w, const float* __restrict__ Phi_b,
    const float* __restrict__ Fbw, const float* __restrict__ Fbb,
    float* __restrict__ out)
{
    extern __shared__ char smem_raw[];
    EncSmem* s = (EncSmem*)smem_raw;

    const int tid = threadIdx.x;
    const int d  = blockIdx.x >> 2;
    const int b0 = (blockIdx.x & 3) * BC;
    const int hk0 = (tid & 15) * 8;
    const int b0t = (tid >> 4) * 4;

    const size_t dHH = (size_t)d * NH * NH;
    const float *Wjd = Wj + dHH, *Wid = Wi + dHH, *Wfd = Wf + dHH, *Wod = Wo + dHH;
    const float *Ujd = Uj + d*NH, *Uid = Ui + d*NH, *Ufd = Uf + d*NH, *Uod = Uo + d*NH;
    const float *bjd = bj + d*NH, *bid = bi_ + d*NH, *bfd = bf + d*NH, *bod = bo + d*NH;
    const float fab = Fab[d];

    for (int i = tid; i < BC*NH; i += 256) (&s->hdup[0][0])[i] = 0ull;
    if (tid < BC) s->den_s[tid] = 0.f;
    if (tid < NH) s->Fa_s[tid] = Fa[d*NH + tid];

    float c[32], num[32], h2[32];
#pragma unroll
    for (int i = 0; i < 32; ++i) { c[i] = 0.f; num[i] = 0.f; }
    __syncthreads();

    for (int t = 0; t < NT; ++t) {
        if (tid < BC) s->xs[tid] = x[((size_t)(b0 + tid)*NT + t)*ND + d];
        __syncthreads();

        cell_step(Wjd,Wid,Wfd,Wod, Ujd,Uid,Ufd,Uod, bjd,bid,bfd,bod,
                  s->hdup, s->xs, hk0, b0t, c, h2);
        __syncthreads();                      // gemm reads of old h done

#pragma unroll
        for (int bb = 0; bb < 4; ++bb) {
            int b = b0t + bb;
#pragma unroll
            for (int cc = 0; cc < 8; ++cc)
                s->hdup[b][hk0 + cc] = dup2(h2[bb*8 + cc]);
            size_t off = O_OFS + (((size_t)(b0 + b)*NT + t)*ND + d)*NH + hk0;
            *(float4*)(out + off)     = make_float4(h2[bb*8+0],h2[bb*8+1],h2[bb*8+2],h2[bb*8+3]);
            *(float4*)(out + off + 4) = make_float4(h2[bb*8+4],h2[bb*8+5],h2[bb*8+6],h2[bb*8+7]);
        }
        __syncthreads();                      // new h visible

        if (tid < BC) {
            const float* hrow = (const float*)&s->hdup[tid][0];
            float sacc = 0.f;
#pragma unroll 4
            for (int k = 0; k < NH; ++k)
                sacc = fmaf(hrow[2*k], s->Fa_s[k], sacc);
            float e = __expf(tanhfast(sacc + fab));
            s->es[tid] = e;
            s->den_s[tid] += e;
            out[A_OFS + ((size_t)(b0 + tid)*NT + t)*ND + d] = e;  // normalized later
        }
        __syncthreads();                      // es visible

#pragma unroll
        for (int bb = 0; bb < 4; ++bb) {
            float e = s->es[b0t + bb];
#pragma unroll
            for (int cc = 0; cc < 8; ++cc)
                num[bb*8+cc] = fmaf(e, h2[bb*8+cc], num[bb*8+cc]);
        }
    }

    // epilogue: g_n, den, h, c; then mu/bt for fc step 0
#pragma unroll
    for (int bb = 0; bb < 4; ++bb) {
        int b = b0t + bb;
        float inv = __fdividef(1.f, s->den_s[b]);
        size_t gofs = ((size_t)d*NB + b0 + b)*NH + hk0;
#pragma unroll
        for (int cc = 0; cc < 8; ++cc) {
            float gn = num[bb*8+cc] * inv;
            s->gs[b][hk0 + cc] = gn;
            g_gn[gofs + cc] = gn;
            g_h[gofs + cc] = h2[bb*8+cc];
            g_c[gofs + cc] = c[bb*8+cc];
        }
    }
    if (tid < BC) g_den[(size_t)(b0 + tid)*ND + d] = s->den_s[tid];
    __syncthreads();

    compute_mu_bt(s, d, b0, tid, Phi_w, Phi_b, Fbw, Fbb);
}

// ================= alphas finalize =================
__global__ void alphas_fin_kernel(float* __restrict__ out) {
    int i = blockIdx.x * 256 + threadIdx.x;
    if (i >= A_CNT) return;
    int b = i / (NT*ND);
    int d = i & (ND-1);
    out[A_OFS + i] = __fdividef(out[A_OFS + i], g_den[(size_t)b*ND + d]);
}

// ================= per-step reduction over D =================
__global__ void __launch_bounds__(32) reduce_kernel(
    int f, const float* __restrict__ proj_w, const float* __restrict__ proj_b,
    float* __restrict__ out)
{
    __shared__ float betas[ND], ys[NOUT];
    int b = blockIdx.x;
    int t = threadIdx.x;
    float bt = g_bt[(size_t)b*ND + t];
    float s = bt;
#pragma unroll
    for (int o = 16; o > 0; o >>= 1) s += __shfl_xor_sync(0xffffffffu, s, o);
    float beta = __fdividef(bt, s);
    betas[t] = beta;
    out[B_OFS + ((size_t)b*NF + f)*ND + t] = beta;
    __syncthreads();

    float y = 0.f;
#pragma unroll
    for (int d = 0; d < ND; ++d)
        y = fmaf(betas[d], g_mu[((size_t)b*ND + d)*NOUT + t], y);
    out[F_OFS + ((size_t)b*NF + f)*NOUT + t] = y;
    ys[t] = y;
    __syncthreads();

    float p = proj_b[t];
#pragma unroll
    for (int o = 0; o < NOUT; ++o)
        p = fmaf(ys[o], proj_w[o*ND + t], p);
    g_prev[(size_t)t*NB + b] = p;
}

// ================= per-step cell + mu/bt =================
__global__ void __launch_bounds__(256, 1) cellmu_kernel(
    const float* __restrict__ Uj, const float* __restrict__ Ui,
    const float* __restrict__ Uf, const float* __restrict__ Uo,
    const float* __restrict__ Wj, const float* __restrict__ Wi,
    const float* __restrict__ Wf, const float* __restrict__ Wo,
    const float* __restrict__ bj, const float* __restrict__ bi_,
    const float* __restrict__ bf, const float* __restrict__ bo,
    const float* __restrict__ Phi_w, const float* __restrict__ Phi_b,
    const float* __restrict__ Fbw, const float* __restrict__ Fbb)
{
    extern __shared__ char smem_raw[];
    EncSmem* s = (EncSmem*)smem_raw;

    const int tid = threadIdx.x;
    const int d  = blockIdx.x >> 2;
    const int b0 = (blockIdx.x & 3) * BC;
    const int hk0 = (tid & 15) * 8;
    const int b0t = (tid >> 4) * 4;

    const size_t dHH = (size_t)d * NH * NH;
    const float *Wjd = Wj + dHH, *Wid = Wi + dHH, *Wfd = Wf + dHH, *Wod = Wo + dHH;
    const float *Ujd = Uj + d*NH, *Uid = Ui + d*NH, *Ufd = Uf + d*NH, *Uod = Uo + d*NH;
    const float *bjd = bj + d*NH, *bid = bi_ + d*NH, *bfd = bf + d*NH, *bod = bo + d*NH;

    for (int i = tid; i < BC*NH; i += 256) {
        int b = i >> 7, k = i & 127;
        size_t gofs = ((size_t)d*NB + b0 + b)*NH + k;
        s->hdup[b][k] = dup2(g_h[gofs]);
        s->gs[b][k]   = g_gn[gofs];
    }
    if (tid < BC) s->xs[tid] = g_prev[(size_t)d*NB + b0 + tid];
    __syncthreads();

    float c[32], h2[32];
#pragma unroll
    for (int bb = 0; bb < 4; ++bb) {
        size_t gofs = ((size_t)d*NB + b0 + b0t + bb)*NH + hk0;
        float4 c0 = *(const float4*)(g_c + gofs);
        float4 c1 = *(const float4*)(g_c + gofs + 4);
        c[bb*8+0]=c0.x; c[bb*8+1]=c0.y; c[bb*8+2]=c0.z; c[bb*8+3]=c0.w;
        c[bb*8+4]=c1.x; c[bb*8+5]=c1.y; c[bb*8+6]=c1.z; c[bb*8+7]=c1.w;
    }

    cell_step(Wjd,Wid,Wfd,Wod, Ujd,Uid,Ufd,Uod, bjd,bid,bfd,bod,
              s->hdup, s->xs, hk0, b0t, c, h2);
    __syncthreads();

#pragma unroll
    for (int bb = 0; bb < 4; ++bb) {
        int b = b0t + bb;
        size_t gofs = ((size_t)d*NB + b0 + b)*NH + hk0;
#pragma unroll
        for (int cc = 0; cc < 8; ++cc) {
            s->hdup[b][hk0 + cc] = dup2(h2[bb*8+cc]);
            g_h[gofs + cc] = h2[bb*8+cc];
            g_c[gofs + cc] = c[bb*8+cc];
        }
    }
    __syncthreads();

    compute_mu_bt(s, d, b0, tid, Phi_w, Phi_b, Fbw, Fbb);
}

// ================= launch =================
extern "C" void kernel_launch(void* const* d_in, const int* in_sizes, int n_in,
                              void* d_out, int out_size) {
    const float* x    = (const float*)d_in[0];
    const float* Uj   = (const float*)d_in[1];
    const float* Ui   = (const float*)d_in[2];
    const float* Uf   = (const float*)d_in[3];
    const float* Uo   = (const float*)d_in[4];
    const float* Wj   = (const float*)d_in[5];
    const float* Wi   = (const float*)d_in[6];
    const float* Wf   = (const float*)d_in[7];
    const float* Wo   = (const float*)d_in[8];
    const float* bj   = (const float*)d_in[9];
    const float* bi   = (const float*)d_in[10];
    const float* bf   = (const float*)d_in[11];
    const float* bo   = (const float*)d_in[12];
    const float* Fa   = (const float*)d_in[13];
    const float* Fab  = (const float*)d_in[14];
    const float* Fbw  = (const float*)d_in[15];
    const float* Fbb  = (const float*)d_in[16];
    const float* Phw  = (const float*)d_in[17];
    const float* Phb  = (const float*)d_in[18];
    const float* prw  = (const float*)d_in[19];
    const float* prb  = (const float*)d_in[20];
    float* out = (float*)d_out;

    int smem = (int)sizeof(EncSmem);
    cudaFuncSetAttribute(enc_kernel,    cudaFuncAttributeMaxDynamicSharedMemorySize, smem);
    cudaFuncSetAttribute(cellmu_kernel, cudaFuncAttributeMaxDynamicSharedMemorySize, smem);

    enc_kernel<<<NCTA, 256, smem>>>(x, Uj,Ui,Uf,Uo, Wj,Wi,Wf,Wo, bj,bi,bf,bo,
                                    Fa, Fab, Phw, Phb, Fbw, Fbb, out);
    alphas_fin_kernel<<<(A_CNT + 255)/256, 256>>>(out);

    for (int f = 0; f < NF; ++f) {
        reduce_kernel<<<NB, 32>>>(f, prw, prb, out);
        if (f < NF - 1)
            cellmu_kernel<<<NCTA, 256, smem>>>(Uj,Ui,Uf,Uo, Wj,Wi,Wf,Wo,
                                               bj,bi,bf,bo, Phw, Phb, Fbw, Fbb);
    }
}